// round 7
// baseline (speedup 1.0000x reference)
#include <cuda_runtime.h>

#define NN 50000
#define NE 800000
#define NBLK 196   // ceil(NN/256)
// F_IN=128, F_HID=64, F_OUT=32

// ---------------- scratch (device globals: alloc-free) ----------------
__device__ __align__(16) float g_dinv[NN];
__device__ __align__(16) float g_H1  [NN * 64];   // (x@W1) * dinv[node]
__device__ __align__(16) float g_AGG1[NN * 64];
__device__ __align__(16) float g_H2  [NN * 32];   // (h@W2) * dinv[node]
__device__ int g_src[NE];
__device__ int g_dst[NE];
__device__ int g_csr_src[NE];
__device__ int g_count  [NN];     // in-degree (no self-loop)
__device__ int g_rowincl[NN];     // inclusive scan within block
__device__ int g_rowstart[NN];
__device__ int g_cursor [NN];
__device__ int g_bsum[NBLK];
__device__ int g_boff[NBLK];
__device__ int g_is64;

// ---------------- init: zero counts + dtype detect ----------------
__global__ void k_init(const unsigned* __restrict__ w) {
    int i = blockIdx.x * 256 + threadIdx.x;
    if (i < NN) g_count[i] = 0;
    if (blockIdx.x == 0 && threadIdx.x == 0) {
        // int64 indices < 50000 => every odd 32-bit word is 0 (in-bounds either way)
        int all0 = 1;
        for (int k = 0; k < 64; k++)
            if (w[2 * k + 1] != 0u) all0 = 0;
        g_is64 = all0;
    }
}

// decode edges to int32 + count in-degree
__global__ void k_prep(const void* __restrict__ p) {
    int e = blockIdx.x * 256 + threadIdx.x;
    if (e >= NE) return;
    int s, d;
    if (g_is64) {
        const long long* q = (const long long*)p;
        s = (int)q[e];  d = (int)q[NE + e];
    } else {
        const int* q = (const int*)p;
        s = q[e];       d = q[NE + e];
    }
    g_src[e] = s;  g_dst[e] = d;
    if ((unsigned)d < NN) atomicAdd(&g_count[d], 1);
}

// ---------------- 3-pass exclusive scan of g_count -> g_rowstart ----------------
__global__ void k_scan_a() {
    __shared__ int sh[256];
    int i = blockIdx.x * 256 + threadIdx.x;
    int v = (i < NN) ? g_count[i] : 0;
    sh[threadIdx.x] = v;
    __syncthreads();
#pragma unroll
    for (int ofs = 1; ofs < 256; ofs <<= 1) {
        int t = (threadIdx.x >= ofs) ? sh[threadIdx.x - ofs] : 0;
        __syncthreads();
        sh[threadIdx.x] += t;
        __syncthreads();
    }
    if (i < NN) g_rowincl[i] = sh[threadIdx.x];
    if (threadIdx.x == 255) g_bsum[blockIdx.x] = sh[255];
}

__global__ void k_scan_b() {
    __shared__ int sh[256];
    int t = threadIdx.x;
    sh[t] = (t < NBLK) ? g_bsum[t] : 0;
    __syncthreads();
#pragma unroll
    for (int ofs = 1; ofs < 256; ofs <<= 1) {
        int v = (t >= ofs) ? sh[t - ofs] : 0;
        __syncthreads();
        sh[t] += v;
        __syncthreads();
    }
    if (t < NBLK) g_boff[t] = (t == 0) ? 0 : sh[t - 1];   // exclusive
}

// rowstart/cursor + dinv (deg = in-count + 1 self loop)
__global__ void k_scan_c() {
    int i = blockIdx.x * 256 + threadIdx.x;
    if (i >= NN) return;
    int c = g_count[i];
    int rs = g_rowincl[i] - c + g_boff[blockIdx.x];
    g_rowstart[i] = rs;
    g_cursor[i]   = rs;
    g_dinv[i] = rsqrtf((float)(c + 1));
}

// fill CSR: csr_src grouped by dst
__global__ void k_fill() {
    int e = blockIdx.x * 256 + threadIdx.x;
    if (e >= NE) return;
    unsigned d = (unsigned)g_dst[e];
    if (d >= NN) return;
    int pos = atomicAdd(&g_cursor[d], 1);
    g_csr_src[pos] = g_src[e];
}

// ---------------- GEMM1: H1 = (x @ W1) * dinv[node] ----------------
__global__ __launch_bounds__(256) void k_gemm1(const float* __restrict__ x,
                                               const float* __restrict__ W1) {
    extern __shared__ float smem[];
    float* Ws = smem;              // 128*64
    float* xs = smem + 128 * 64;   // 128*130 (pad 2)
    const int t = threadIdx.x;
    const int node0 = blockIdx.x * 128;

    for (int i = t; i < 128 * 64 / 4; i += 256)
        ((float4*)Ws)[i] = ((const float4*)W1)[i];
    for (int i = t; i < 128 * 128; i += 256) {
        int row = i >> 7, col = i & 127;
        int node = node0 + row;
        xs[row * 130 + col] = (node < NN) ? x[node * 128 + col] : 0.0f;
    }
    __syncthreads();

    const int ng = t >> 3;   // 4 nodes each
    const int cg = t & 7;    // 8 cols each
    float acc[4][8];
#pragma unroll
    for (int i = 0; i < 4; i++)
#pragma unroll
        for (int j = 0; j < 8; j++) acc[i][j] = 0.0f;

    const float* xp = xs + ng * 4 * 130;
    const float* wp = Ws + cg * 8;
#pragma unroll 2
    for (int k = 0; k < 128; k++) {
        float4 w0 = *(const float4*)(wp + k * 64);
        float4 w1 = *(const float4*)(wp + k * 64 + 4);
        float xv[4];
#pragma unroll
        for (int i = 0; i < 4; i++) xv[i] = xp[i * 130 + k];
#pragma unroll
        for (int i = 0; i < 4; i++) {
            acc[i][0] += xv[i] * w0.x; acc[i][1] += xv[i] * w0.y;
            acc[i][2] += xv[i] * w0.z; acc[i][3] += xv[i] * w0.w;
            acc[i][4] += xv[i] * w1.x; acc[i][5] += xv[i] * w1.y;
            acc[i][6] += xv[i] * w1.z; acc[i][7] += xv[i] * w1.w;
        }
    }

#pragma unroll
    for (int i = 0; i < 4; i++) {
        int node = node0 + ng * 4 + i;
        if (node < NN) {
            float s = g_dinv[node];
            float4 v0 = make_float4(acc[i][0]*s, acc[i][1]*s, acc[i][2]*s, acc[i][3]*s);
            float4 v1 = make_float4(acc[i][4]*s, acc[i][5]*s, acc[i][6]*s, acc[i][7]*s);
            ((float4*)(g_H1 + node * 64 + cg * 8))[0] = v0;
            ((float4*)(g_H1 + node * 64 + cg * 8))[1] = v1;
        }
    }
}

// ---------------- gather layer 1: AGG1[n] = H1[n] + sum_{s in N(n)} H1[s] ----------------
// one warp per node, float2 per lane (64 cols), 8-deep unroll for MLP
__global__ __launch_bounds__(256) void k_agg1() {
    int warp = (blockIdx.x * 256 + threadIdx.x) >> 5;
    int lane = threadIdx.x & 31;
    if (warp >= NN) return;
    const int start = g_rowstart[warp];
    const int len   = g_count[warp];
    float2 acc = ((const float2*)(g_H1 + (size_t)warp * 64))[lane];  // self loop
    int j = 0;
    for (; j + 8 <= len; j += 8) {
        int s[8];
#pragma unroll
        for (int u = 0; u < 8; u++) s[u] = g_csr_src[start + j + u];
        float2 v[8];
#pragma unroll
        for (int u = 0; u < 8; u++) v[u] = ((const float2*)(g_H1 + (size_t)s[u] * 64))[lane];
#pragma unroll
        for (int u = 0; u < 8; u++) { acc.x += v[u].x; acc.y += v[u].y; }
    }
    for (; j < len; j++) {
        int s = g_csr_src[start + j];
        float2 v = ((const float2*)(g_H1 + (size_t)s * 64))[lane];
        acc.x += v.x; acc.y += v.y;
    }
    ((float2*)(g_AGG1 + (size_t)warp * 64))[lane] = acc;
}

// ---------------- GEMM2: h = relu(dinv*AGG1 + b1); H2 = (h@W2)*dinv ----------------
__global__ __launch_bounds__(256) void k_gemm2(const float* __restrict__ W2,
                                               const float* __restrict__ b1) {
    __shared__ float Ws[64 * 32];
    __shared__ float hs[128 * 66];   // pad 2
    const int t = threadIdx.x;
    const int node0 = blockIdx.x * 128;

    for (int i = t; i < 64 * 32; i += 256) Ws[i] = W2[i];
    for (int i = t; i < 128 * 64; i += 256) {
        int row = i >> 6, col = i & 63;
        int node = node0 + row;
        float h = 0.0f;
        if (node < NN) h = fmaxf(fmaf(g_dinv[node], g_AGG1[node * 64 + col], b1[col]), 0.0f);
        hs[row * 66 + col] = h;
    }
    __syncthreads();

    const int ng = t >> 3;   // 4 nodes
    const int cg = t & 7;    // 4 cols
    float acc[4][4];
#pragma unroll
    for (int i = 0; i < 4; i++)
#pragma unroll
        for (int j = 0; j < 4; j++) acc[i][j] = 0.0f;

    const float* hp = hs + ng * 4 * 66;
    const float* wp = Ws + cg * 4;
#pragma unroll 4
    for (int k = 0; k < 64; k++) {
        float4 w = *(const float4*)(wp + k * 32);
        float hv[4];
#pragma unroll
        for (int i = 0; i < 4; i++) hv[i] = hp[i * 66 + k];
#pragma unroll
        for (int i = 0; i < 4; i++) {
            acc[i][0] += hv[i] * w.x; acc[i][1] += hv[i] * w.y;
            acc[i][2] += hv[i] * w.z; acc[i][3] += hv[i] * w.w;
        }
    }

#pragma unroll
    for (int i = 0; i < 4; i++) {
        int node = node0 + ng * 4 + i;
        if (node < NN) {
            float s = g_dinv[node];
            float4 h2 = make_float4(acc[i][0]*s, acc[i][1]*s, acc[i][2]*s, acc[i][3]*s);
            ((float4*)(g_H2 + node * 32 + cg * 4))[0] = h2;
        }
    }
}

// ---------------- gather layer 2 + final: out[n] = dinv[n]*(H2[n]+sum H2[s]) + b2 ----------------
// one warp per node, 1 float per lane (32 cols)
__global__ __launch_bounds__(256) void k_agg2(float* __restrict__ out,
                                              const float* __restrict__ b2) {
    int warp = (blockIdx.x * 256 + threadIdx.x) >> 5;
    int lane = threadIdx.x & 31;
    if (warp >= NN) return;
    const int start = g_rowstart[warp];
    const int len   = g_count[warp];
    float acc = g_H2[(size_t)warp * 32 + lane];   // self loop
    int j = 0;
    for (; j + 8 <= len; j += 8) {
        int s[8];
#pragma unroll
        for (int u = 0; u < 8; u++) s[u] = g_csr_src[start + j + u];
        float v[8];
#pragma unroll
        for (int u = 0; u < 8; u++) v[u] = g_H2[(size_t)s[u] * 32 + lane];
#pragma unroll
        for (int u = 0; u < 8; u++) acc += v[u];
    }
    for (; j < len; j++)
        acc += g_H2[(size_t)g_csr_src[start + j] * 32 + lane];
    out[(size_t)warp * 32 + lane] = fmaf(acc, g_dinv[warp], b2[lane]);
}

// ---------------- launch ----------------
extern "C" void kernel_launch(void* const* d_in, const int* in_sizes, int n_in,
                              void* d_out, int out_size) {
    const float* x  = (const float*)d_in[0];
    const void*  ei = d_in[1];
    const float* W1 = (const float*)d_in[2];
    const float* b1 = (const float*)d_in[3];
    const float* W2 = (const float*)d_in[4];
    const float* b2 = (const float*)d_in[5];
    float* out = (float*)d_out;

    const int smem1 = (128 * 64 + 128 * 130) * sizeof(float);  // 99328 B
    cudaFuncSetAttribute(k_gemm1, cudaFuncAttributeMaxDynamicSharedMemorySize, smem1);

    k_init   <<<NBLK, 256>>>((const unsigned*)ei);
    k_prep   <<<(NE + 255) / 256, 256>>>(ei);
    k_scan_a <<<NBLK, 256>>>();
    k_scan_b <<<1, 256>>>();
    k_scan_c <<<NBLK, 256>>>();
    k_fill   <<<(NE + 255) / 256, 256>>>();
    k_gemm1  <<<(NN + 127) / 128, 256, smem1>>>(x, W1);
    k_agg1   <<<(NN * 32 + 255) / 256, 256>>>();
    k_gemm2  <<<(NN + 127) / 128, 256>>>(W2, b1);
    k_agg2   <<<(NN * 32 + 255) / 256, 256>>>(out, b2);
}

// round 9
// speedup vs baseline: 1.2378x; 1.2378x over previous
#include <cuda_runtime.h>

#define NN 50000
#define NE 800000
// F_IN=128, F_HID=64, F_OUT=32

// ---------------- scratch (device globals: alloc-free) ----------------
__device__ __align__(16) float g_deg [NN];
__device__ __align__(16) float g_dinv[NN];
__device__ __align__(16) float g_H1  [NN * 64];   // (x@W1) * dinv[node]  (pre-scaled)
__device__ __align__(16) float g_AGG1[NN * 64];
__device__ __align__(16) float g_H2  [NN * 32];   // (h@W2) * dinv[node]  (pre-scaled)
__device__ int g_src[NE];
__device__ int g_dst[NE];
__device__ int g_is64;

// ---------------- init: deg=1 (self-loop) + edge dtype detect ----------------
// int64 indices < 50000 => every odd 32-bit word is 0. Probe is in-bounds for both layouts.
__global__ void k_init(const unsigned* __restrict__ w) {
    int i = blockIdx.x * 256 + threadIdx.x;
    if (i < NN) g_deg[i] = 1.0f;
    if (blockIdx.x == 0 && threadIdx.x == 0) {
        int all0 = 1;
        for (int k = 0; k < 64; k++)
            if (w[2 * k + 1] != 0u) all0 = 0;
        g_is64 = all0;
    }
}

// decode edge_index to int32 + accumulate degree, 2 edges per thread
__global__ void k_prep(const void* __restrict__ p) {
    int e0 = (blockIdx.x * 256 + threadIdx.x) * 2;
    if (e0 >= NE) return;
#pragma unroll
    for (int u = 0; u < 2; u++) {
        int e = e0 + u;
        if (e >= NE) break;
        int s, d;
        if (g_is64) {
            const long long* q = (const long long*)p;
            s = (int)q[e];  d = (int)q[NE + e];
        } else {
            const int* q = (const int*)p;
            s = q[e];       d = q[NE + e];
        }
        g_src[e] = s;  g_dst[e] = d;
        if ((unsigned)d < NN) atomicAdd(&g_deg[d], 1.0f);
    }
}

// ---------------- GEMM1: H1s = (x @ W1) * dinv ; AGG1 = H1s (self-loop init) ; store dinv ----------------
__global__ __launch_bounds__(256) void k_gemm1(const float* __restrict__ x,
                                               const float* __restrict__ W1) {
    extern __shared__ float smem[];
    float* Ws = smem;              // 128*64
    float* xs = smem + 128 * 64;   // 128*130 (pad 2)
    const int t = threadIdx.x;
    const int node0 = blockIdx.x * 128;

    for (int i = t; i < 128 * 64 / 4; i += 256)
        ((float4*)Ws)[i] = ((const float4*)W1)[i];
    for (int i = t; i < 128 * 128; i += 256) {
        int row = i >> 7, col = i & 127;
        int node = node0 + row;
        xs[row * 130 + col] = (node < NN) ? x[node * 128 + col] : 0.0f;
    }
    __syncthreads();

    const int ng = t >> 3;   // 4 nodes each
    const int cg = t & 7;    // 8 cols each
    float acc[4][8];
#pragma unroll
    for (int i = 0; i < 4; i++)
#pragma unroll
        for (int j = 0; j < 8; j++) acc[i][j] = 0.0f;

    const float* xp = xs + ng * 4 * 130;
    const float* wp = Ws + cg * 8;
#pragma unroll 2
    for (int k = 0; k < 128; k++) {
        float4 w0 = *(const float4*)(wp + k * 64);
        float4 w1 = *(const float4*)(wp + k * 64 + 4);
        float xv[4];
#pragma unroll
        for (int i = 0; i < 4; i++) xv[i] = xp[i * 130 + k];
#pragma unroll
        for (int i = 0; i < 4; i++) {
            acc[i][0] += xv[i] * w0.x; acc[i][1] += xv[i] * w0.y;
            acc[i][2] += xv[i] * w0.z; acc[i][3] += xv[i] * w0.w;
            acc[i][4] += xv[i] * w1.x; acc[i][5] += xv[i] * w1.y;
            acc[i][6] += xv[i] * w1.z; acc[i][7] += xv[i] * w1.w;
        }
    }

#pragma unroll
    for (int i = 0; i < 4; i++) {
        int node = node0 + ng * 4 + i;
        if (node < NN) {
            float s = rsqrtf(g_deg[node]);
            g_dinv[node] = s;
            float4 v0 = make_float4(acc[i][0]*s, acc[i][1]*s, acc[i][2]*s, acc[i][3]*s);
            float4 v1 = make_float4(acc[i][4]*s, acc[i][5]*s, acc[i][6]*s, acc[i][7]*s);
            ((float4*)(g_H1   + node * 64 + cg * 8))[0] = v0;
            ((float4*)(g_H1   + node * 64 + cg * 8))[1] = v1;
            ((float4*)(g_AGG1 + node * 64 + cg * 8))[0] = v0;
            ((float4*)(g_AGG1 + node * 64 + cg * 8))[1] = v1;
        }
    }
}

// ---------------- scatter layer 1: AGG1[dst] += H1s[src] ----------------
__global__ void k_scatter1() {
    int i = blockIdx.x * 256 + threadIdx.x;
    if (i >= NE * 16) return;
    int e = i >> 4, c = i & 15;
    unsigned src = (unsigned)g_src[e];
    unsigned dst = (unsigned)g_dst[e];
    if (src >= NN || dst >= NN) return;
    float4 v = ((const float4*)g_H1)[src * 16 + c];
    atomicAdd(((float4*)g_AGG1) + dst * 16 + c, v);
}

// ---------------- GEMM2: h = relu(dinv*AGG1 + b1); H2s = (h@W2)*dinv ; out init = H2s ----------------
__global__ __launch_bounds__(256) void k_gemm2(const float* __restrict__ W2,
                                               const float* __restrict__ b1,
                                               float* __restrict__ out) {
    __shared__ float Ws[64 * 32];
    __shared__ float hs[128 * 66];   // pad 2
    const int t = threadIdx.x;
    const int node0 = blockIdx.x * 128;

    for (int i = t; i < 64 * 32; i += 256) Ws[i] = W2[i];
    for (int i = t; i < 128 * 64; i += 256) {
        int row = i >> 6, col = i & 63;
        int node = node0 + row;
        float h = 0.0f;
        if (node < NN) h = fmaxf(fmaf(g_dinv[node], g_AGG1[node * 64 + col], b1[col]), 0.0f);
        hs[row * 66 + col] = h;
    }
    __syncthreads();

    const int ng = t >> 3;   // 4 nodes
    const int cg = t & 7;    // 4 cols
    float acc[4][4];
#pragma unroll
    for (int i = 0; i < 4; i++)
#pragma unroll
        for (int j = 0; j < 4; j++) acc[i][j] = 0.0f;

    const float* hp = hs + ng * 4 * 66;
    const float* wp = Ws + cg * 4;
#pragma unroll 4
    for (int k = 0; k < 64; k++) {
        float4 w = *(const float4*)(wp + k * 32);
        float hv[4];
#pragma unroll
        for (int i = 0; i < 4; i++) hv[i] = hp[i * 66 + k];
#pragma unroll
        for (int i = 0; i < 4; i++) {
            acc[i][0] += hv[i] * w.x; acc[i][1] += hv[i] * w.y;
            acc[i][2] += hv[i] * w.z; acc[i][3] += hv[i] * w.w;
        }
    }

#pragma unroll
    for (int i = 0; i < 4; i++) {
        int node = node0 + ng * 4 + i;
        if (node < NN) {
            float s = g_dinv[node];
            float4 h2 = make_float4(acc[i][0]*s, acc[i][1]*s, acc[i][2]*s, acc[i][3]*s);
            ((float4*)(g_H2 + node * 32 + cg * 4))[0] = h2;
            ((float4*)(out  + node * 32 + cg * 4))[0] = h2;
        }
    }
}

// ---------------- scatter layer 2: out[dst] += H2s[src] ----------------
__global__ void k_scatter2(float* __restrict__ out) {
    int i = blockIdx.x * 256 + threadIdx.x;
    if (i >= NE * 8) return;
    int e = i >> 3, c = i & 7;
    unsigned src = (unsigned)g_src[e];
    unsigned dst = (unsigned)g_dst[e];
    if (src >= NN || dst >= NN) return;
    float4 v = ((const float4*)g_H2)[src * 8 + c];
    atomicAdd(((float4*)out) + dst * 8 + c, v);
}

// ---------------- final: out = out * dinv[node] + b2 ----------------
__global__ void k_final(float* __restrict__ out, const float* __restrict__ b2) {
    int i = blockIdx.x * 256 + threadIdx.x;
    if (i >= NN * 8) return;
    int node = i >> 3, cb = (i & 7) * 4;
    float s = g_dinv[node];
    float4 v = ((float4*)out)[i];
    float4 bb = *(const float4*)(b2 + cb);
    ((float4*)out)[i] = make_float4(fmaf(v.x, s, bb.x), fmaf(v.y, s, bb.y),
                                    fmaf(v.z, s, bb.z), fmaf(v.w, s, bb.w));
}

// ---------------- launch ----------------
extern "C" void kernel_launch(void* const* d_in, const int* in_sizes, int n_in,
                              void* d_out, int out_size) {
    const float* x  = (const float*)d_in[0];
    const void*  ei = d_in[1];
    const float* W1 = (const float*)d_in[2];
    const float* b1 = (const float*)d_in[3];
    const float* W2 = (const float*)d_in[4];
    const float* b2 = (const float*)d_in[5];
    float* out = (float*)d_out;

    const int smem1 = (128 * 64 + 128 * 130) * sizeof(float);  // 99328 B
    cudaFuncSetAttribute(k_gemm1, cudaFuncAttributeMaxDynamicSharedMemorySize, smem1);

    k_init    <<<(NN + 255) / 256, 256>>>((const unsigned*)ei);
    k_prep    <<<(NE / 2 + 255) / 256, 256>>>(ei);
    k_gemm1   <<<(NN + 127) / 128, 256, smem1>>>(x, W1);
    k_scatter1<<<(NE * 16 + 255) / 256, 256>>>();
    k_gemm2   <<<(NN + 127) / 128, 256>>>(W2, b1, out);
    k_scatter2<<<(NE * 8 + 255) / 256, 256>>>(out);
    k_final   <<<(NN * 8 + 255) / 256, 256>>>(out, b2);
}